// round 16
// baseline (speedup 1.0000x reference)
#include <cuda_runtime.h>
#include <math.h>
#include <stdint.h>
#include <mma.h>

using namespace nvcuda;

#define TT    1024
#define DIM   512
#define NG    8
#define NE    8
#define NPAIR 64
#define HDIM  1024

__device__ int   d_cnt[NPAIR];
__device__ int   d_tok[NPAIR][TT];
__device__ int   d_asg[NPAIR][TT];
__device__ int   d_pid[TT * 4];        // pair id per assignment (for bias in combine)
__device__ float d_w[TT * 4];
__device__ float d_H[TT * 4][HDIM];
__device__ float d_Yp[2][TT * 4][DIM]; // split-K partials for layer 2

// round-to-nearest tf32 conversion (unbiased)
__device__ __forceinline__ float tf32r(float v) {
    uint32_t r;
    asm("cvt.rna.tf32.f32 %0, %1;" : "=r"(r) : "f"(v));
    return __uint_as_float(r);
}
__device__ __forceinline__ uint32_t smem_u32(const void* p) {
    uint32_t a;
    asm("{ .reg .u64 t; cvta.to.shared.u64 t, %1; cvt.u32.u64 %0, t; }" : "=r"(a) : "l"(p));
    return a;
}
__device__ __forceinline__ void cp16(uint32_t s, const void* g) {
    asm volatile("cp.async.cg.shared.global [%0], [%1], 16;" :: "r"(s), "l"(g));
}
#define CP_COMMIT() asm volatile("cp.async.commit_group;" ::: "memory")
#define CP_WAIT0()  asm volatile("cp.async.wait_group 0;" ::: "memory")

// B enters the MMA as raw fp32 bits (HW tf32 truncation, bias ~ -2^-11):
// correct the systematic scale in the epilogue. A is rna-rounded (unbiased).
#define CORR 1.00048828125f

// ---------------- kernel 0: reset pair counters ----------------
__global__ void zero_cnt_kernel() {
    if (threadIdx.x < NPAIR) d_cnt[threadIdx.x] = 0;
}

// ---------------- kernel 1: routing (one warp per token) ----------------
__global__ void route_kernel(const float* __restrict__ x,
                             const float* __restrict__ g1,
                             const float* __restrict__ g2) {
    int t = (blockIdx.x * blockDim.x + threadIdx.x) >> 5;
    int lane = threadIdx.x & 31;
    if (t >= TT) return;
    const float* xt = x + (size_t)t * DIM;

    float a[NG];
#pragma unroll
    for (int g = 0; g < NG; g++) a[g] = 0.f;
    for (int i = lane; i < DIM; i += 32) {
        float xv = xt[i];
        const float* gp = g1 + (size_t)i * NG;
#pragma unroll
        for (int g = 0; g < NG; g++) a[g] += xv * gp[g];
    }
#pragma unroll
    for (int off = 16; off; off >>= 1)
#pragma unroll
        for (int g = 0; g < NG; g++) a[g] += __shfl_xor_sync(0xffffffffu, a[g], off);

    int i1 = 0; float v1 = a[0];
#pragma unroll
    for (int g = 1; g < NG; g++) if (a[g] > v1) { v1 = a[g]; i1 = g; }
    int i2 = -1; float v2 = -1e30f;
#pragma unroll
    for (int g = 0; g < NG; g++) if (g != i1 && a[g] > v2) { v2 = a[g]; i2 = g; }
    float e2 = expf(v2 - v1);
    float inv = 1.f / (1.f + e2);
    int   gs[2]  = { i1, i2 };
    float c1w[2] = { inv, e2 * inv };

    float b[2 * NE];
#pragma unroll
    for (int q = 0; q < 2 * NE; q++) b[q] = 0.f;
    const float* p0base = g2 + (size_t)gs[0] * DIM * NE;
    const float* p1base = g2 + (size_t)gs[1] * DIM * NE;
    for (int i = lane; i < DIM; i += 32) {
        float xv = xt[i];
        const float* p0 = p0base + (size_t)i * NE;
        const float* p1 = p1base + (size_t)i * NE;
#pragma unroll
        for (int e = 0; e < NE; e++) { b[e] += xv * p0[e]; b[NE + e] += xv * p1[e]; }
    }
#pragma unroll
    for (int off = 16; off; off >>= 1)
#pragma unroll
        for (int q = 0; q < 2 * NE; q++) b[q] += __shfl_xor_sync(0xffffffffu, b[q], off);

    if (lane == 0) {
#pragma unroll
        for (int r = 0; r < 2; r++) {
            int j1 = 0; float u1 = b[r * NE + 0];
#pragma unroll
            for (int e = 1; e < NE; e++) if (b[r * NE + e] > u1) { u1 = b[r * NE + e]; j1 = e; }
            int j2 = -1; float u2 = -1e30f;
#pragma unroll
            for (int e = 0; e < NE; e++) if (e != j1 && b[r * NE + e] > u2) { u2 = b[r * NE + e]; j2 = e; }
            float f2   = expf(u2 - u1);
            float inv2 = 1.f / (1.f + f2);
            int   pe[2]  = { j1, j2 };
            float c2w[2] = { inv2, f2 * inv2 };
            int g = gs[r];
#pragma unroll
            for (int rr = 0; rr < 2; rr++) {
                int pair = g * NE + pe[rr];
                int slot = r * 2 + rr;
                int pos  = atomicAdd(&d_cnt[pair], 1);
                d_tok[pair][pos] = t;
                d_asg[pair][pos] = t * 4 + slot;
                d_w[t * 4 + slot] = c1w[r] * c2w[rr];
                d_pid[t * 4 + slot] = pair;
            }
        }
    }
}

// ---------- WMMA tf32 grouped GEMM: paired k-chunks, one barrier per pair ------
// Per CTA: (pair, 128-col n-tile[, K-half]). BM=64, BN=128, BK=32, KT=512/CTA,
// TWO 32-k chunks consumed per iteration (one CP_WAIT0 + one __syncthreads each).
// 128 threads = 4 warps in 2x2 grid, warp tile 32x64 (6 frag loads / 8 MMAs per
// kk-step, 8 independent accumulators). B staged via cp.async.cg into 4 buffers
// in half-rotation: pair it+1 is issued right after sync(it) and lands during
// compute(it). A via register prefetch + rna cvt into 4 half-rotating buffers.
// HW tf32 truncation on B; CORR scale fix in epilogue.
// smem (dynamic, bytes):
//   0:      A bufs 4 x 64x36 f  (36864)
//   36864:  B bufs 4 x 32x132 f (67584)  [aliased as Cs 64x132 in epilogue]
//   104448: bsm[128] | 104960: rp[64] ptr | 105472: atb[64] int -> 105728
#define AB_OFF 0
#define BB_OFF 36864
#define SMEM_DYN 105728

template <int KT, int KFULL, int NTOT, bool RELU, bool SPLIT>
__global__ __launch_bounds__(128, 2) void moe_gemm_wmma(const float* __restrict__ Xg,
                                                        const float* __restrict__ Wt,
                                                        const float* __restrict__ bias) {
    constexpr int BM = 64, BN = 128, BK = 32, NIT = KT / (2 * BK);
    constexpr int LDA = 36, LDB = 132, LDC = 132;
    const int pair  = blockIdx.y;
    const int count = d_cnt[pair];
    if (count == 0) return;
    const int n0    = blockIdx.x * BN;
    const int kbase = SPLIT ? (int)blockIdx.z * KT : 0;

    const float* Xsrc = SPLIT ? &d_H[0][0] : Xg;
    float*       Out  = SPLIT ? &d_Yp[blockIdx.z][0][0] : &d_H[0][0];
    const int*   rows = SPLIT ? d_asg[pair] : d_tok[pair];
    const float* Wp   = Wt + (size_t)pair * KFULL * NTOT + (size_t)kbase * NTOT + n0;
    const float* bp   = bias + (size_t)pair * NTOT + n0;

    extern __shared__ __align__(16) char smem[];
    float* const Abase = (float*)(smem + AB_OFF);
    float* const Bbase = (float*)(smem + BB_OFF);
    float* const bsm   = (float*)(smem + 104448);
    const float** rp   = (const float**)(smem + 104960);
    int*   atb         = (int*)(smem + 105472);
    const uint32_t sb  = smem_u32(smem);

    const int tid = threadIdx.x;
    const int wid = tid >> 5;
    const int wm  = wid >> 1;     // 0..1 (32-row half)
    const int wn  = wid & 1;      // 0..1 (64-col half)

    if (!SPLIT) bsm[tid] = bp[tid];

    // staging coords: A 4 chunks/thread over 64x32, B 8 chunks/thread over 32x128
    int ar[4], ak[4];
#pragma unroll
    for (int i = 0; i < 4; i++) {
        int q = tid + i * 128;
        ar[i] = q >> 3; ak[i] = (q & 7) * 4;
    }
    const int brr = tid >> 5;         // base row 0..3 (+4 rows per chunk)
    const int bcc = (tid & 31) * 4;   // col

    for (int m0 = 0; m0 < count; m0 += BM) {
        if (tid < BM) {
            int m = m0 + tid;
            rp[tid]  = (m < count) ? (Xsrc + (size_t)rows[m] * KFULL + kbase) : (const float*)0;
            atb[tid] = (m < count) ? d_asg[pair][m] : 0;
        }
        __syncthreads();

        const float* arow[4];
#pragma unroll
        for (int i = 0; i < 4; i++) arow[i] = rp[ar[i]];

        wmma::fragment<wmma::accumulator, 16, 16, 8, float> acc[2][4];
#pragma unroll
        for (int i = 0; i < 2; i++)
#pragma unroll
            for (int j = 0; j < 4; j++) wmma::fill_fragment(acc[i][j], 0.f);

        // prologue: issue B pair 0 (chunks 0,1 -> bufs 0,1), one group
#pragma unroll
        for (int j = 0; j < 2; j++) {
            uint32_t base = sb + BB_OFF + j * 16896;
            const int k0 = j * BK;
#pragma unroll
            for (int i = 0; i < 8; i++) {
                int r = brr + i * 4;
                cp16(base + (uint32_t)(r * LDB + bcc) * 4, Wp + (size_t)(k0 + r) * NTOT + bcc);
            }
        }
        CP_COMMIT();
        // A prefetch pair 0
        float4 pa[2][4];
#pragma unroll
        for (int j = 0; j < 2; j++)
#pragma unroll
            for (int i = 0; i < 4; i++) {
                pa[j][i] = make_float4(0.f, 0.f, 0.f, 0.f);
                if (arow[i]) pa[j][i] = *reinterpret_cast<const float4*>(arow[i] + j * BK + ak[i]);
            }

        for (int it = 0; it < NIT; it++) {
            const int half = (it & 1) * 2;
            // commit A pair it from registers (rna-rounded)
#pragma unroll
            for (int j = 0; j < 2; j++) {
                float* Ac = Abase + (half + j) * 2304;
#pragma unroll
                for (int i = 0; i < 4; i++) {
                    float* a = Ac + ar[i] * LDA + ak[i];
                    a[0] = tf32r(pa[j][i].x); a[1] = tf32r(pa[j][i].y);
                    a[2] = tf32r(pa[j][i].z); a[3] = tf32r(pa[j][i].w);
                }
            }
            CP_WAIT0();              // B pair it arrived
            __syncthreads();         // A + B for pair it visible; prior readers done

            if (it + 1 < NIT) {
                const int nhalf = ((it + 1) & 1) * 2;
                // issue B pair it+1 (lands during compute of pair it)
#pragma unroll
                for (int j = 0; j < 2; j++) {
                    uint32_t base = sb + BB_OFF + (nhalf + j) * 16896;
                    const int k0 = (2 * (it + 1) + j) * BK;
#pragma unroll
                    for (int i = 0; i < 8; i++) {
                        int r = brr + i * 4;
                        cp16(base + (uint32_t)(r * LDB + bcc) * 4, Wp + (size_t)(k0 + r) * NTOT + bcc);
                    }
                }
                CP_COMMIT();
                // A prefetch pair it+1
#pragma unroll
                for (int j = 0; j < 2; j++)
#pragma unroll
                    for (int i = 0; i < 4; i++) {
                        pa[j][i] = make_float4(0.f, 0.f, 0.f, 0.f);
                        if (arow[i]) pa[j][i] = *reinterpret_cast<const float4*>(
                            arow[i] + (2 * (it + 1) + j) * BK + ak[i]);
                    }
            }

            // compute both chunks of pair it
#pragma unroll
            for (int cc = 0; cc < 2; cc++) {
                const float* Ac = Abase + (half + cc) * 2304;
                const float* Bc = Bbase + (half + cc) * 4224;
#pragma unroll
                for (int kk = 0; kk < BK; kk += 8) {
                    wmma::fragment<wmma::matrix_a, 16, 16, 8, wmma::precision::tf32, wmma::row_major> af[2];
                    wmma::fragment<wmma::matrix_b, 16, 16, 8, wmma::precision::tf32, wmma::row_major> bf[4];
#pragma unroll
                    for (int i = 0; i < 2; i++)
                        wmma::load_matrix_sync(af[i], Ac + (wm * 32 + i * 16) * LDA + kk, LDA);
#pragma unroll
                    for (int j = 0; j < 4; j++)
                        wmma::load_matrix_sync(bf[j], Bc + kk * LDB + wn * 64 + j * 16, LDB);
#pragma unroll
                    for (int i = 0; i < 2; i++)
#pragma unroll
                        for (int j = 0; j < 4; j++)
                            wmma::mma_sync(acc[i][j], af[i], bf[j], acc[i][j]);
                }
            }
        }

        // epilogue: reuse B pool as Cs
        __syncthreads();
        float* const Cs = Bbase;
#pragma unroll
        for (int i = 0; i < 2; i++)
#pragma unroll
            for (int j = 0; j < 4; j++)
                wmma::store_matrix_sync(Cs + (wm * 32 + i * 16) * LDC + wn * 64 + j * 16,
                                        acc[i][j], LDC, wmma::mem_row_major);
        __syncthreads();

#pragma unroll
        for (int it = 0; it < 16; it++) {
            int f = tid + it * 128;           // float4 index over 64x128
            int row = f >> 5;
            int col = (f & 31) * 4;
            int m = m0 + row;
            if (m < count) {
                const float* cr = Cs + row * LDC + col;
                float4 v;
                if (SPLIT) {
                    v.x = cr[0] * CORR; v.y = cr[1] * CORR;
                    v.z = cr[2] * CORR; v.w = cr[3] * CORR;
                } else {
                    v.x = cr[0] * CORR + bsm[col + 0];
                    v.y = cr[1] * CORR + bsm[col + 1];
                    v.z = cr[2] * CORR + bsm[col + 2];
                    v.w = cr[3] * CORR + bsm[col + 3];
                    if (RELU) {
                        v.x = fmaxf(v.x, 0.f); v.y = fmaxf(v.y, 0.f);
                        v.z = fmaxf(v.z, 0.f); v.w = fmaxf(v.w, 0.f);
                    }
                }
                *reinterpret_cast<float4*>(Out + (size_t)atb[row] * NTOT + n0 + col) = v;
            }
        }
        __syncthreads();
    }
}

// ---------------- kernel 4: reduce split-K halves + bias, weighted combine ----
__global__ void combine_kernel(const float* __restrict__ b2, float* __restrict__ out) {
    int t = blockIdx.x;
    float w[4];
    const float* bb[4];
#pragma unroll
    for (int s = 0; s < 4; s++) {
        w[s]  = d_w[t * 4 + s];
        bb[s] = b2 + (size_t)d_pid[t * 4 + s] * DIM;
    }
    for (int i = threadIdx.x; i < DIM; i += blockDim.x) {
        float acc = 0.f;
#pragma unroll
        for (int s = 0; s < 4; s++) {
            int asg = t * 4 + s;
            acc += w[s] * (d_Yp[0][asg][i] + d_Yp[1][asg][i] + bb[s][i]);
        }
        out[(size_t)t * DIM + i] = acc;
    }
}

// ---------------- launch ----------------
extern "C" void kernel_launch(void* const* d_in, const int* in_sizes, int n_in,
                              void* d_out, int out_size) {
    const float* x  = (const float*)d_in[0];
    const float* g1 = (const float*)d_in[1];
    const float* g2 = (const float*)d_in[2];
    const float* W1 = (const float*)d_in[3];
    const float* b1 = (const float*)d_in[4];
    const float* W2 = (const float*)d_in[5];
    const float* b2 = (const float*)d_in[6];
    float* out = (float*)d_out;

    cudaFuncSetAttribute(moe_gemm_wmma<DIM, DIM, HDIM, true, false>,
                         cudaFuncAttributeMaxDynamicSharedMemorySize, SMEM_DYN);
    cudaFuncSetAttribute(moe_gemm_wmma<DIM, HDIM, DIM, false, true>,
                         cudaFuncAttributeMaxDynamicSharedMemorySize, SMEM_DYN);

    zero_cnt_kernel<<<1, 64>>>();
    route_kernel<<<(TT * 32) / 128, 128>>>(x, g1, g2);
    // layer 1: [count,512] @ [512,1024] + b1, relu -> d_H            (512 CTAs)
    moe_gemm_wmma<DIM, DIM, HDIM, true, false>
        <<<dim3(HDIM / 128, NPAIR, 1), 128, SMEM_DYN>>>(x, W1, b1);
    // layer 2: [count,1024] @ [1024,512], split-K x2 -> d_Yp         (512 CTAs)
    moe_gemm_wmma<DIM, HDIM, DIM, false, true>
        <<<dim3(DIM / 128, NPAIR, 2), 128, SMEM_DYN>>>(x, W2, b2);
    combine_kernel<<<TT, 128>>>(b2, out);
}

// round 17
// speedup vs baseline: 2.9355x; 2.9355x over previous
#include <cuda_runtime.h>
#include <cuda_fp16.h>
#include <math.h>
#include <stdint.h>
#include <mma.h>

using namespace nvcuda;

#define TT    1024
#define DIM   512
#define NG    8
#define NE    8
#define NPAIR 64
#define HDIM  1024

__device__ int    d_cnt[NPAIR];
__device__ int    d_tok[NPAIR][TT];
__device__ int    d_asg[NPAIR][TT];
__device__ int    d_pid[TT * 4];
__device__ float  d_w[TT * 4];
__device__ __half d_H16[TT * 4][HDIM];   // layer-1 activations, fp16
__device__ float  d_Yp[2][TT * 4][DIM];  // split-K partials for layer 2

__device__ __forceinline__ uint32_t f22h(float a, float b) {
    __half2 h = __floats2half2_rn(a, b);
    return *reinterpret_cast<uint32_t*>(&h);
}

// ---------------- kernel 0: reset pair counters ----------------
__global__ void zero_cnt_kernel() {
    if (threadIdx.x < NPAIR) d_cnt[threadIdx.x] = 0;
}

// ---------------- kernel 1: routing (one warp per token) ----------------
__global__ void route_kernel(const float* __restrict__ x,
                             const float* __restrict__ g1,
                             const float* __restrict__ g2) {
    int t = (blockIdx.x * blockDim.x + threadIdx.x) >> 5;
    int lane = threadIdx.x & 31;
    if (t >= TT) return;
    const float* xt = x + (size_t)t * DIM;

    float a[NG];
#pragma unroll
    for (int g = 0; g < NG; g++) a[g] = 0.f;
    for (int i = lane; i < DIM; i += 32) {
        float xv = xt[i];
        const float* gp = g1 + (size_t)i * NG;
#pragma unroll
        for (int g = 0; g < NG; g++) a[g] += xv * gp[g];
    }
#pragma unroll
    for (int off = 16; off; off >>= 1)
#pragma unroll
        for (int g = 0; g < NG; g++) a[g] += __shfl_xor_sync(0xffffffffu, a[g], off);

    int i1 = 0; float v1 = a[0];
#pragma unroll
    for (int g = 1; g < NG; g++) if (a[g] > v1) { v1 = a[g]; i1 = g; }
    int i2 = -1; float v2 = -1e30f;
#pragma unroll
    for (int g = 0; g < NG; g++) if (g != i1 && a[g] > v2) { v2 = a[g]; i2 = g; }
    float e2 = expf(v2 - v1);
    float inv = 1.f / (1.f + e2);
    int   gs[2]  = { i1, i2 };
    float c1w[2] = { inv, e2 * inv };

    float b[2 * NE];
#pragma unroll
    for (int q = 0; q < 2 * NE; q++) b[q] = 0.f;
    const float* p0base = g2 + (size_t)gs[0] * DIM * NE;
    const float* p1base = g2 + (size_t)gs[1] * DIM * NE;
    for (int i = lane; i < DIM; i += 32) {
        float xv = xt[i];
        const float* p0 = p0base + (size_t)i * NE;
        const float* p1 = p1base + (size_t)i * NE;
#pragma unroll
        for (int e = 0; e < NE; e++) { b[e] += xv * p0[e]; b[NE + e] += xv * p1[e]; }
    }
#pragma unroll
    for (int off = 16; off; off >>= 1)
#pragma unroll
        for (int q = 0; q < 2 * NE; q++) b[q] += __shfl_xor_sync(0xffffffffu, b[q], off);

    if (lane == 0) {
#pragma unroll
        for (int r = 0; r < 2; r++) {
            int j1 = 0; float u1 = b[r * NE + 0];
#pragma unroll
            for (int e = 1; e < NE; e++) if (b[r * NE + e] > u1) { u1 = b[r * NE + e]; j1 = e; }
            int j2 = -1; float u2 = -1e30f;
#pragma unroll
            for (int e = 0; e < NE; e++) if (e != j1 && b[r * NE + e] > u2) { u2 = b[r * NE + e]; j2 = e; }
            float f2   = expf(u2 - u1);
            float inv2 = 1.f / (1.f + f2);
            int   pe[2]  = { j1, j2 };
            float c2w[2] = { inv2, f2 * inv2 };
            int g = gs[r];
#pragma unroll
            for (int rr = 0; rr < 2; rr++) {
                int pair = g * NE + pe[rr];
                int slot = r * 2 + rr;
                int pos  = atomicAdd(&d_cnt[pair], 1);
                d_tok[pair][pos] = t;
                d_asg[pair][pos] = t * 4 + slot;
                d_w[t * 4 + slot] = c1w[r] * c2w[rr];
                d_pid[t * 4 + slot] = pair;
            }
        }
    }
}

// ---------- fp16 WMMA grouped GEMM (R14 skeleton, full-rate HMMA) --------------
// Per CTA: (pair, 128-col n-tile[, K-half]). BM=64, BN=128, BK=32, KT=512/CTA,
// 16 stages, ONE __syncthreads per stage. 128 threads = 4 warps 2x2, warp tile
// 32x64 via m16n16k16 fp16 (fp32 acc). Both operands LDG->rne-cvt at prefetch
// time (half2 regs: A 8, B 16), committed as STS.64 into fp16 double buffers.
// Layer1 reads fp32 x; layer2 reads fp16 d_H16 directly (no cvt).
// smem: pool [0,33792) = {A 2x64x40h, B 2x32x136h} aliased by Cs 64x132 f32;
//       33792 bsm | 34304 rp (char* x64) | 34816 atb -> 35072
#define SMEM_DYN 35072

template <int KT, int KFULL, int NTOT, bool RELU, bool SPLIT>
__global__ __launch_bounds__(128, 3) void moe_gemm_h(const float* __restrict__ Xf,
                                                     const float* __restrict__ Wt,
                                                     const float* __restrict__ bias) {
    constexpr int BM = 64, BN = 128, BK = 32, NKC = KT / BK;
    constexpr int LDA_H = 40, LDB_H = 136, LDC = 132;
    const int pair  = blockIdx.y;
    const int count = d_cnt[pair];
    if (count == 0) return;
    const int n0    = blockIdx.x * BN;
    const int kbase = SPLIT ? (int)blockIdx.z * KT : 0;

    const int*   rows = SPLIT ? d_asg[pair] : d_tok[pair];
    const float* Wp   = Wt + (size_t)pair * KFULL * NTOT + (size_t)kbase * NTOT + n0;
    const float* bp   = bias + (size_t)pair * NTOT + n0;

    extern __shared__ __align__(16) char smem[];
    __half* const A16 = (__half*)(smem + 0);        // 2 bufs, 2560 halves each
    __half* const B16 = (__half*)(smem + 10240);    // 2 bufs, 4352 halves each
    float*  const bsm = (float*)(smem + 33792);
    const char** rp   = (const char**)(smem + 34304);
    int*    atb       = (int*)(smem + 34816);

    const int tid = threadIdx.x;
    const int wid = tid >> 5;
    const int wm  = wid >> 1;     // 0..1 (32-row half)
    const int wn  = wid & 1;      // 0..1 (64-col half)

    if (!SPLIT) bsm[tid] = bp[tid];

    // staging coords: A 4 chunks/thread (4 k-elems each) over 64x32,
    //                 B 8 rows/thread (4 n-elems each) over 32x128
    int ar[4], ak[4];
#pragma unroll
    for (int i = 0; i < 4; i++) {
        int q = tid + i * 128;
        ar[i] = q >> 3; ak[i] = (q & 7) * 4;
    }
    const int brr = tid >> 5;
    const int bcc = (tid & 31) * 4;

    for (int m0 = 0; m0 < count; m0 += BM) {
        if (tid < BM) {
            int m = m0 + tid;
            if (m < count) {
                rp[tid] = SPLIT
                    ? (const char*)&d_H16[rows[m]][kbase]
                    : (const char*)(Xf + (size_t)rows[m] * KFULL);
                atb[tid] = d_asg[pair][m];
            } else { rp[tid] = 0; atb[tid] = 0; }
        }
        __syncthreads();

        const char* arow[4];
#pragma unroll
        for (int i = 0; i < 4; i++) arow[i] = rp[ar[i]];

        wmma::fragment<wmma::accumulator, 16, 16, 16, float> acc[2][4];
#pragma unroll
        for (int i = 0; i < 2; i++)
#pragma unroll
            for (int j = 0; j < 4; j++) wmma::fill_fragment(acc[i][j], 0.f);

        // prefetch stage 0 into half2 regs
        uint32_t pa[4][2], pb[8][2];
#pragma unroll
        for (int i = 0; i < 4; i++) {
            pa[i][0] = 0u; pa[i][1] = 0u;
            if (arow[i]) {
                if (SPLIT) {
                    uint2 v = *(const uint2*)(arow[i] + (size_t)ak[i] * 2);
                    pa[i][0] = v.x; pa[i][1] = v.y;
                } else {
                    float4 v = *(const float4*)(arow[i] + (size_t)ak[i] * 4);
                    pa[i][0] = f22h(v.x, v.y); pa[i][1] = f22h(v.z, v.w);
                }
            }
        }
#pragma unroll
        for (int i = 0; i < 8; i++) {
            int r = brr + i * 4;
            float4 w = *(const float4*)(Wp + (size_t)r * NTOT + bcc);
            pb[i][0] = f22h(w.x, w.y); pb[i][1] = f22h(w.z, w.w);
        }

        for (int c = 0; c < NKC; c++) {
            // commit stage c regs into buffer c&1
            __half* Ac = A16 + (c & 1) * 2560;
            __half* Bc = B16 + (c & 1) * 4352;
#pragma unroll
            for (int i = 0; i < 4; i++)
                *(uint2*)&Ac[ar[i] * LDA_H + ak[i]] = make_uint2(pa[i][0], pa[i][1]);
#pragma unroll
            for (int i = 0; i < 8; i++) {
                int r = brr + i * 4;
                *(uint2*)&Bc[r * LDB_H + bcc] = make_uint2(pb[i][0], pb[i][1]);
            }
            __syncthreads();

            if (c + 1 < NKC) {     // prefetch stage c+1 (overlaps compute below)
                const int kn = (c + 1) * BK;
#pragma unroll
                for (int i = 0; i < 4; i++) {
                    pa[i][0] = 0u; pa[i][1] = 0u;
                    if (arow[i]) {
                        if (SPLIT) {
                            uint2 v = *(const uint2*)(arow[i] + (size_t)(kn + ak[i]) * 2);
                            pa[i][0] = v.x; pa[i][1] = v.y;
                        } else {
                            float4 v = *(const float4*)(arow[i] + (size_t)(kn + ak[i]) * 4);
                            pa[i][0] = f22h(v.x, v.y); pa[i][1] = f22h(v.z, v.w);
                        }
                    }
                }
#pragma unroll
                for (int i = 0; i < 8; i++) {
                    int r = brr + i * 4;
                    float4 w = *(const float4*)(Wp + (size_t)(kn + r) * NTOT + bcc);
                    pb[i][0] = f22h(w.x, w.y); pb[i][1] = f22h(w.z, w.w);
                }
            }

            // compute: 2 kk-steps of k16
#pragma unroll
            for (int kk = 0; kk < 2; kk++) {
                wmma::fragment<wmma::matrix_a, 16, 16, 16, __half, wmma::row_major> af[2];
                wmma::fragment<wmma::matrix_b, 16, 16, 16, __half, wmma::row_major> bf[4];
#pragma unroll
                for (int i = 0; i < 2; i++)
                    wmma::load_matrix_sync(af[i], Ac + (wm * 32 + i * 16) * LDA_H + kk * 16, LDA_H);
#pragma unroll
                for (int j = 0; j < 4; j++)
                    wmma::load_matrix_sync(bf[j], Bc + (kk * 16) * LDB_H + wn * 64 + j * 16, LDB_H);
#pragma unroll
                for (int i = 0; i < 2; i++)
#pragma unroll
                    for (int j = 0; j < 4; j++)
                        wmma::mma_sync(acc[i][j], af[i], bf[j], acc[i][j]);
            }
        }

        // epilogue: reuse pool as Cs (fp32)
        __syncthreads();
        float* const Cs = (float*)smem;
#pragma unroll
        for (int i = 0; i < 2; i++)
#pragma unroll
            for (int j = 0; j < 4; j++)
                wmma::store_matrix_sync(Cs + (wm * 32 + i * 16) * LDC + wn * 64 + j * 16,
                                        acc[i][j], LDC, wmma::mem_row_major);
        __syncthreads();

#pragma unroll
        for (int it = 0; it < 16; it++) {
            int f = tid + it * 128;           // float4 index over 64x128
            int row = f >> 5;
            int col = (f & 31) * 4;
            int m = m0 + row;
            if (m < count) {
                const float* cr = Cs + row * LDC + col;
                if (SPLIT) {
                    float4 v = make_float4(cr[0], cr[1], cr[2], cr[3]);
                    *(float4*)(&d_Yp[blockIdx.z][0][0] + (size_t)atb[row] * NTOT + n0 + col) = v;
                } else {
                    float v0 = cr[0] + bsm[col + 0];
                    float v1 = cr[1] + bsm[col + 1];
                    float v2 = cr[2] + bsm[col + 2];
                    float v3 = cr[3] + bsm[col + 3];
                    if (RELU) {
                        v0 = fmaxf(v0, 0.f); v1 = fmaxf(v1, 0.f);
                        v2 = fmaxf(v2, 0.f); v3 = fmaxf(v3, 0.f);
                    }
                    *(uint2*)&d_H16[atb[row]][n0 + col] = make_uint2(f22h(v0, v1), f22h(v2, v3));
                }
            }
        }
        __syncthreads();
    }
}

// ---------------- kernel 4: reduce split-K halves + bias, weighted combine ----
__global__ void combine_kernel(const float* __restrict__ b2, float* __restrict__ out) {
    int t = blockIdx.x;
    float w[4];
    const float* bb[4];
#pragma unroll
    for (int s = 0; s < 4; s++) {
        w[s]  = d_w[t * 4 + s];
        bb[s] = b2 + (size_t)d_pid[t * 4 + s] * DIM;
    }
    for (int i = threadIdx.x; i < DIM; i += blockDim.x) {
        float acc = 0.f;
#pragma unroll
        for (int s = 0; s < 4; s++) {
            int asg = t * 4 + s;
            acc += w[s] * (d_Yp[0][asg][i] + d_Yp[1][asg][i] + bb[s][i]);
        }
        out[(size_t)t * DIM + i] = acc;
    }
}

// ---------------- launch ----------------
extern "C" void kernel_launch(void* const* d_in, const int* in_sizes, int n_in,
                              void* d_out, int out_size) {
    const float* x  = (const float*)d_in[0];
    const float* g1 = (const float*)d_in[1];
    const float* g2 = (const float*)d_in[2];
    const float* W1 = (const float*)d_in[3];
    const float* b1 = (const float*)d_in[4];
    const float* W2 = (const float*)d_in[5];
    const float* b2 = (const float*)d_in[6];
    float* out = (float*)d_out;

    cudaFuncSetAttribute(moe_gemm_h<DIM, DIM, HDIM, true, false>,
                         cudaFuncAttributeMaxDynamicSharedMemorySize, SMEM_DYN);
    cudaFuncSetAttribute(moe_gemm_h<DIM, HDIM, DIM, false, true>,
                         cudaFuncAttributeMaxDynamicSharedMemorySize, SMEM_DYN);

    zero_cnt_kernel<<<1, 64>>>();
    route_kernel<<<(TT * 32) / 128, 128>>>(x, g1, g2);
    // layer 1: [count,512] @ [512,1024] + b1, relu -> d_H16 (fp16)   (512 CTAs)
    moe_gemm_h<DIM, DIM, HDIM, true, false>
        <<<dim3(HDIM / 128, NPAIR, 1), 128, SMEM_DYN>>>(x, W1, b1);
    // layer 2: [count,1024] @ [1024,512], split-K x2 -> d_Yp         (512 CTAs)
    moe_gemm_h<DIM, HDIM, DIM, false, true>
        <<<dim3(DIM / 128, NPAIR, 2), 128, SMEM_DYN>>>(x, W2, b2);
    combine_kernel<<<TT, 128>>>(b2, out);
}